// round 8
// baseline (speedup 1.0000x reference)
#include <cuda_runtime.h>
#include <cuda_bf16.h>
#include <math.h>
#include <stdint.h>

#define SEQ   1024
#define DM    1024
#define HN    16
#define HDIM  64
#define NSAMP 8
#define INTER 768
#define BATCH 4
#define EPS   1e-5f

typedef __nv_bfloat16 bf16;

// ---------------- scratch (device globals; no allocations allowed) ----------
__device__ float g_hsmean[BATCH * DM];
__device__ float g_partial[BATCH * 16 * DM];
__device__ int   g_expert[NSAMP];
__device__ int   g_need[8];
__device__ float g_w[NSAMP];
__device__ bf16  g_hb[(size_t)BATCH * SEQ * DM];
__device__ bf16  g_qkvb[(size_t)NSAMP * SEQ * 3 * DM];       // 48 MB
__device__ bf16  g_ctxb[(size_t)NSAMP * SEQ * DM];           // 16 MB
__device__ float g_ao[(size_t)NSAMP * SEQ * DM];             // 32 MB
__device__ float g_x1[(size_t)NSAMP * SEQ * DM];             // 32 MB
__device__ bf16  g_x1b[(size_t)NSAMP * SEQ * DM];            // 16 MB
__device__ bf16  g_gub[(size_t)NSAMP * SEQ * 2 * INTER];     // 24 MB
__device__ bf16  g_actb[(size_t)NSAMP * SEQ * INTER];        // 12 MB
__device__ float g_mlp[(size_t)NSAMP * SEQ * DM];            // 32 MB
// all-expert bf16 weights
#define WB_QKV 0LL
#define WB_WO  25165824LL
#define WB_GU  33554432LL
#define WB_WD  46137344LL
#define WB_TOTAL 52428800LL
__device__ bf16 g_wb[WB_TOTAL];                              // 105 MB

// ---------------- small helpers ----------------------------------------------
__device__ __forceinline__ float block_reduce_sum(float v, float* sh) {
    int tid = threadIdx.x;
    #pragma unroll
    for (int o = 16; o; o >>= 1) v += __shfl_down_sync(0xFFFFFFFFu, v, o);
    if ((tid & 31) == 0) sh[tid >> 5] = v;
    __syncthreads();
    float r = 0.f;
    if (tid < 32) {
        float x = (tid < (int)(blockDim.x >> 5)) ? sh[tid] : 0.f;
        #pragma unroll
        for (int o = 16; o; o >>= 1) x += __shfl_down_sync(0xFFFFFFFFu, x, o);
        if (tid == 0) sh[0] = x;
    }
    __syncthreads();
    r = sh[0];
    __syncthreads();
    return r;
}

__device__ __forceinline__ void mma_bf16(float* d, const uint32_t* a, const uint32_t* b) {
    asm volatile(
        "mma.sync.aligned.m16n8k16.row.col.f32.bf16.bf16.f32 "
        "{%0,%1,%2,%3},{%4,%5,%6,%7},{%8,%9},{%0,%1,%2,%3};"
        : "+f"(d[0]), "+f"(d[1]), "+f"(d[2]), "+f"(d[3])
        : "r"(a[0]), "r"(a[1]), "r"(a[2]), "r"(a[3]), "r"(b[0]), "r"(b[1]));
}

__device__ __forceinline__ void ldsm_x4(uint32_t* r, uint32_t addr) {
    asm volatile(
        "ldmatrix.sync.aligned.m8n8.x4.shared.b16 {%0,%1,%2,%3}, [%4];"
        : "=r"(r[0]), "=r"(r[1]), "=r"(r[2]), "=r"(r[3]) : "r"(addr));
}
__device__ __forceinline__ void ldsm_x2t(uint32_t* r, uint32_t addr) {
    asm volatile(
        "ldmatrix.sync.aligned.m8n8.x2.trans.shared.b16 {%0,%1}, [%2];"
        : "=r"(r[0]), "=r"(r[1]) : "r"(addr));
}
__device__ __forceinline__ uint32_t lds32(uint32_t a) {
    uint32_t v;
    asm volatile("ld.shared.b32 %0, [%1];" : "=r"(v) : "r"(a));
    return v;
}
__device__ __forceinline__ uint32_t packbf(float hi, float lo) {
    uint32_t r;
    asm("cvt.rn.bf16x2.f32 %0, %1, %2;" : "=r"(r) : "f"(hi), "f"(lo));
    return r;
}

__device__ __forceinline__ void cp16(uint32_t s, const void* g) {
    asm volatile("cp.async.cg.shared.global [%0], [%1], 16;" :: "r"(s), "l"(g));
}
__device__ __forceinline__ void cp_commit() {
    asm volatile("cp.async.commit_group;" ::: "memory");
}
__device__ __forceinline__ void cp_wait0() {
    asm volatile("cp.async.wait_group 0;" ::: "memory");
}
__device__ __forceinline__ void cp_wait1() {
    asm volatile("cp.async.wait_group 1;" ::: "memory");
}

// ---------------- fp32 -> bf16 conversion ------------------------------------
__global__ void cvt_bf16(const float4* __restrict__ s, uint2* __restrict__ d, int n4) {
    int i = blockIdx.x * blockDim.x + threadIdx.x;
    if (i < n4) {
        float4 v = s[i];
        uint2 o;
        o.x = packbf(v.y, v.x);
        o.y = packbf(v.w, v.z);
        d[i] = o;
    }
}

// convert expert weights only if routed (g_need flag)
__global__ void cvt_w(const float4* __restrict__ s, uint2* __restrict__ d,
                      int n4, int perExp4) {
    int i = blockIdx.x * blockDim.x + threadIdx.x;
    if (i >= n4) return;
    if (!g_need[i / perExp4]) return;
    float4 v = s[i];
    uint2 o;
    o.x = packbf(v.y, v.x);
    o.y = packbf(v.w, v.z);
    d[i] = o;
}

// ---------------- routing ----------------------------------------------------
__global__ void mean1_kernel(const float* __restrict__ hidden) {
    int b = blockIdx.x, c = blockIdx.y;
    int tid = threadIdx.x;
    float acc[4] = {0.f, 0.f, 0.f, 0.f};
    for (int s = c * 64; s < c * 64 + 64; s++) {
        const float* row = hidden + ((size_t)b * SEQ + s) * DM;
        #pragma unroll
        for (int i = 0; i < 4; i++) acc[i] += row[tid + i * 256];
    }
    #pragma unroll
    for (int i = 0; i < 4; i++)
        g_partial[((size_t)b * 16 + c) * DM + tid + i * 256] = acc[i];
}

__global__ void mean2_kernel() {
    int b = blockIdx.x;
    int tid = threadIdx.x;
    #pragma unroll
    for (int i = 0; i < 4; i++) {
        int d = tid + i * 256;
        float s = 0.f;
        for (int c = 0; c < 16; c++) s += g_partial[((size_t)b * 16 + c) * DM + d];
        g_hsmean[b * DM + d] = s * (1.0f / (float)SEQ);
    }
}

__global__ void routing_kernel(const float* __restrict__ Wr,
                               const float* __restrict__ temperature,
                               float* __restrict__ out_logits) {
    int tid = threadIdx.x;          // 1024
    int w = tid >> 5, lane = tid & 31;
    int b = w >> 3, c = w & 7;
    float s = 0.f;
    for (int d = lane; d < DM; d += 32)
        s += g_hsmean[b * DM + d] * Wr[c * DM + d];
    #pragma unroll
    for (int o = 16; o; o >>= 1) s += __shfl_down_sync(0xFFFFFFFFu, s, o);
    __shared__ float logits[32];
    if (lane == 0) logits[w] = s;
    if (tid < 8) g_need[tid] = 0;
    __syncthreads();
    if (tid < BATCH) {
        float t = fminf(fmaxf(temperature[0], 0.1f), 10.0f);
        float lv[8];
        #pragma unroll
        for (int cc = 0; cc < 8; cc++) {
            lv[cc] = logits[tid * 8 + cc] / t;
            out_logits[tid * 8 + cc] = lv[cc];
        }
        int i0 = 0;
        #pragma unroll
        for (int cc = 1; cc < 8; cc++) if (lv[cc] > lv[i0]) i0 = cc;
        int i1 = -1;
        #pragma unroll
        for (int cc = 0; cc < 8; cc++) {
            if (cc == i0) continue;
            if (i1 < 0 || lv[cc] > lv[i1]) i1 = cc;
        }
        float e = expf(lv[i1] - lv[i0]);
        g_expert[2 * tid]     = i0;
        g_expert[2 * tid + 1] = i1;
        g_w[2 * tid]     = 1.0f / (1.0f + e);
        g_w[2 * tid + 1] = e / (1.0f + e);
        g_need[i0] = 1;
        g_need[i1] = 1;
    }
}

// ---------------- bf16 tensor-core GEMM v5 -------------------------------------
// CTA tile 256x128, BK=64, warp tile 64x64 (8 warps), 3-stage cp.async.
#define ASTG 144                    // A row stride bytes (64 bf16 + 8 pad)
#define BSTG 272                    // B row stride bytes (128 bf16 + 8 pad)
#define ABY (256 * ASTG)            // 36864
#define BBY (64 * BSTG)             // 17408
#define STG5 (ABY + BBY)            // 54272
#define GEMM_SMEM (3 * STG5)        // 162816

template<int OBF>
__global__ __launch_bounds__(256, 1) void gemm_bf(
    const bf16* __restrict__ Ab, const bf16* __restrict__ Bb, void* __restrict__ Cb,
    int N, int K, int lda, long long strideA, int a_div2, long long strideC)
{
    extern __shared__ char smraw[];
    uint32_t sb = (uint32_t)__cvta_generic_to_shared(smraw);
    int z = blockIdx.z;
    const bf16* A = Ab + (size_t)(a_div2 ? (z >> 1) : z) * strideA;
    const bf16* B = Bb + (long long)g_expert[z] * ((long long)K * N);
    int m0 = blockIdx.y * 256;
    int n0 = blockIdx.x * 128;
    int tid = threadIdx.x, lane = tid & 31, wid = tid >> 5;
    int wm0 = (wid & 3) * 64;       // 4 M-warps x 2 N-warps, warp tile 64x64
    int wn0 = (wid >> 2) * 64;

    auto load_tile = [&](int k0, int buf) {
        uint32_t base = sb + (uint32_t)(buf * STG5);
        #pragma unroll
        for (int p = 0; p < 8; p++) {
            int i = tid + p * 256;
            int row = i >> 3, ch = i & 7;
            cp16(base + (uint32_t)(row * ASTG + ch * 16),
                 A + (size_t)(m0 + row) * lda + k0 + ch * 8);
        }
        #pragma unroll
        for (int p = 0; p < 4; p++) {
            int i = tid + p * 256;
            int row = i >> 4, ch = i & 15;
            cp16(base + (uint32_t)(ABY + row * BSTG + ch * 16),
                 B + (size_t)(k0 + row) * N + n0 + ch * 8);
        }
    };

    int NT = K / 64;
    load_tile(0, 0);
    cp_commit();
    load_tile(64, 1);
    cp_commit();

    float acc[4][8][4];
    #pragma unroll
    for (int i = 0; i < 4; i++)
        #pragma unroll
        for (int j = 0; j < 8; j++)
            #pragma unroll
            for (int q = 0; q < 4; q++) acc[i][j][q] = 0.f;

    uint32_t af[2][4][4];

    int buf = 0;
    for (int tI = 0; tI < NT; ++tI) {
        if (tI + 1 < NT) cp_wait1(); else cp_wait0();
        __syncthreads();
        if (tI + 2 < NT) {
            int nb = buf + 2; if (nb >= 3) nb -= 3;
            load_tile((tI + 2) * 64, nb);
            cp_commit();
        }
        uint32_t stage = sb + (uint32_t)(buf * STG5);
        uint32_t aB = stage + (uint32_t)((wm0 + (lane & 15)) * ASTG + (lane >> 4) * 16);
        uint32_t bB = stage + (uint32_t)(ABY + (lane & 15) * BSTG + wn0 * 2);

        #pragma unroll
        for (int i = 0; i < 4; i++) ldsm_x4(af[0][i], aB + (uint32_t)(i * 16 * ASTG));

        #pragma unroll
        for (int ks = 0; ks < 4; ks++) {
            int cb = ks & 1, nb2 = cb ^ 1;
            uint32_t bfr[8][2];
            #pragma unroll
            for (int j = 0; j < 8; j++)
                ldsm_x2t(bfr[j], bB + (uint32_t)(ks * 16 * BSTG + j * 16));
            if (ks < 3) {
                #pragma unroll
                for (int i = 0; i < 4; i++)
                    ldsm_x4(af[nb2][i], aB + (uint32_t)(i * 16 * ASTG + (ks + 1) * 32));
            }
            #pragma unroll
            for (int i = 0; i < 4; i++)
                #pragma unroll
                for (int j = 0; j < 8; j++)
                    mma_bf16(acc[i][j], af[cb][i], bfr[j]);
        }
        buf++; if (buf == 3) buf = 0;
    }

    int g = lane >> 2, t = lane & 3;
    #pragma unroll
    for (int i = 0; i < 4; i++) {
        #pragma unroll
        for (int j = 0; j < 8; j++) {
            int r = m0 + wm0 + i * 16 + g;
            int c = n0 + wn0 + j * 8 + 2 * t;
            if (OBF) {
                bf16* C = (bf16*)Cb + (size_t)z * strideC;
                *(uint32_t*)(C + (size_t)r * N + c) = packbf(acc[i][j][1], acc[i][j][0]);
                *(uint32_t*)(C + (size_t)(r + 8) * N + c) = packbf(acc[i][j][3], acc[i][j][2]);
            } else {
                float* C = (float*)Cb + (size_t)z * strideC;
                *(float2*)(C + (size_t)r * N + c) = make_float2(acc[i][j][0], acc[i][j][1]);
                *(float2*)(C + (size_t)(r + 8) * N + c) = make_float2(acc[i][j][2], acc[i][j][3]);
            }
        }
    }
}

// ---------------- RoPE (in-place on bf16 q,k) ---------------------------------
__global__ void rope_kernel(const float* __restrict__ cosb, const float* __restrict__ sinb) {
    int s = blockIdx.x, n = blockIdx.y;
    int tid = threadIdx.x;            // 512
    int h = tid >> 5, j = tid & 31;
    float c0 = cosb[s * HDIM + j],      s0 = sinb[s * HDIM + j];
    float c1 = cosb[s * HDIM + j + 32], s1 = sinb[s * HDIM + j + 32];
    bf16* row = g_qkvb + ((size_t)n * SEQ + s) * (3 * DM);
    bf16* q = row + h * HDIM;
    float qa = __bfloat162float(q[j]), qb = __bfloat162float(q[j + 32]);
    q[j]      = __float2bfloat16(qa * c0 - qb * s0);
    q[j + 32] = __float2bfloat16(qb * c1 + qa * s1);
    bf16* k = row + DM + h * HDIM;
    float ka = __bfloat162float(k[j]), kb = __bfloat162float(k[j + 32]);
    k[j]      = __float2bfloat16(ka * c0 - kb * s0);
    k[j + 32] = __float2bfloat16(kb * c1 + ka * s1);
}

// ---------------- flash attention (bf16 mma) -----------------------------------
#define FQ 0
#define FK 9216
#define FV (9216 * 3)
#define FLASH_SMEM (9216 * 5)

__global__ __launch_bounds__(128) void flash_kernel() {
    extern __shared__ char smraw[];
    uint32_t sb = (uint32_t)__cvta_generic_to_shared(smraw);

    int nh = blockIdx.y;
    int n = nh >> 4, h = nh & 15;
    int q0 = blockIdx.x * 64;
    const bf16* qbase = g_qkvb + (size_t)n * SEQ * (3 * DM) + h * HDIM;
    const bf16* kbase = qbase + DM;
    const bf16* vbase = qbase + 2 * DM;

    int tid = threadIdx.x, lane = tid & 31, wid = tid >> 5;
    int g = lane >> 2, t = lane & 3;
    int wm0 = wid * 16;

    #pragma unroll
    for (int p = 0; p < 4; p++) {
        int i = tid + p * 128;
        int row = i >> 3, ch = i & 7;
        cp16(sb + (uint32_t)(FQ + row * 144 + ch * 16),
             qbase + (size_t)(q0 + row) * (3 * DM) + ch * 8);
        cp16(sb + (uint32_t)(FK + row * 144 + ch * 16),
             kbase + (size_t)row * (3 * DM) + ch * 8);
        cp16(sb + (uint32_t)(FV + row * 144 + ch * 16),
             vbase + (size_t)row * (3 * DM) + ch * 8);
    }
    cp_commit();
    cp_wait0();
    __syncthreads();

    uint32_t qf[4][4];
    uint32_t qA = sb + (uint32_t)(FQ + (wm0 + (lane & 15)) * 144 + (lane >> 4) * 16);
    #pragma unroll
    for (int kc = 0; kc < 4; kc++) ldsm_x4(qf[kc], qA + (uint32_t)(kc * 32));

    float m0 = -INFINITY, m1 = -INFINITY, l0 = 0.f, l1 = 0.f;
    float oa[8][4];
    #pragma unroll
    for (int j = 0; j < 8; j++)
        #pragma unroll
        for (int q = 0; q < 4; q++) oa[j][q] = 0.f;

    const int NT = SEQ / 64;
    for (int it = 0; it < NT; it++) {
        int buf = it & 1;
        if (it + 1 < NT) {
            int kv = (it + 1) * 64;
            int ob = buf ^ 1;
            #pragma unroll
            for (int p = 0; p < 4; p++) {
                int i = tid + p * 128;
                int row = i >> 3, ch = i & 7;
                cp16(sb + (uint32_t)(FK + ob * 9216 + row * 144 + ch * 16),
                     kbase + (size_t)(kv + row) * (3 * DM) + ch * 8);
                cp16(sb + (uint32_t)(FV + ob * 9216 + row * 144 + ch * 16),
                     vbase + (size_t)(kv + row) * (3 * DM) + ch * 8);
            }
            cp_commit();
        }
        uint32_t kB = sb + (uint32_t)(FK + buf * 9216);
        uint32_t vB = sb + (uint32_t)(FV + buf * 9216);

        float sacc[8][4];
        #pragma unroll
        for (int j = 0; j < 8; j++)
            #pragma unroll
            for (int q = 0; q < 4; q++) sacc[j][q] = 0.f;

        #pragma unroll
        for (int kc = 0; kc < 4; kc++) {
            #pragma unroll
            for (int nt = 0; nt < 8; nt++) {
                uint32_t ba = kB + (uint32_t)((nt * 8 + g) * 144 + kc * 32 + t * 4);
                uint32_t bb[2];
                bb[0] = lds32(ba);
                bb[1] = lds32(ba + 16);
                mma_bf16(sacc[nt], qf[kc], bb);
            }
        }

        float rm0 = -INFINITY, rm1 = -INFINITY;
        #pragma unroll
        for (int nt = 0; nt < 8; nt++) {
            #pragma unroll
            for (int q = 0; q < 4; q++) sacc[nt][q] *= 0.125f;
            rm0 = fmaxf(rm0, fmaxf(sacc[nt][0], sacc[nt][1]));
            rm1 = fmaxf(rm1, fmaxf(sacc[nt][2], sacc[nt][3]));
        }
        rm0 = fmaxf(rm0, __shfl_xor_sync(0xFFFFFFFFu, rm0, 1));
        rm0 = fmaxf(rm0, __shfl_xor_sync(0xFFFFFFFFu, rm0, 2));
        rm1 = fmaxf(rm1, __shfl_xor_sync(0xFFFFFFFFu, rm1, 1));
        rm1 = fmaxf(rm1, __shfl_xor_sync(0xFFFFFFFFu, rm1, 2));
        float mn0 = fmaxf(m0, rm0), mn1 = fmaxf(m1, rm1);
        float c0 = __expf(m0 - mn0), c1 = __expf(m1 - mn1);
        float ls0 = 0.f, ls1 = 0.f;
        #pragma unroll
        for (int nt = 0; nt < 8; nt++) {
            sacc[nt][0] = __expf(sacc[nt][0] - mn0);
            sacc[nt][1] = __expf(sacc[nt][1] - mn0);
            sacc[nt][2] = __expf(sacc[nt][2] - mn1);
            sacc[nt][3] = __expf(sacc[nt][3] - mn1);
            ls0 += sacc[nt][0] + sacc[nt][1];
            ls1 += sacc[nt][2] + sacc[nt][3];
        }
        ls0 += __shfl_xor_sync(0xFFFFFFFFu, ls0, 1);
        ls0 += __shfl_xor_sync(0xFFFFFFFFu, ls0, 2);
        ls1 += __shfl_xor_sync(0xFFFFFFFFu, ls1, 1);
        ls1 += __shfl_xor_sync(0xFFFFFFFFu, ls1, 2);
        l0 = l0 * c0 + ls0;
        l1 = l1 * c1 + ls1;
        m0 = mn0; m1 = mn1;
        #pragma unroll
        for (int j = 0; j < 8; j++) {
            oa[j][0] *= c0; oa[j][1] *= c0;
            oa[j][2] *= c1; oa[j][3] *= c1;
        }

        #pragma unroll
        for (int mC = 0; mC < 4; mC++) {
            uint32_t pa[4];
            pa[0] = packbf(sacc[2 * mC][1],     sacc[2 * mC][0]);
            pa[1] = packbf(sacc[2 * mC][3],     sacc[2 * mC][2]);
            pa[2] = packbf(sacc[2 * mC + 1][1], sacc[2 * mC + 1][0]);
            pa[3] = packbf(sacc[2 * mC + 1][3], sacc[2 * mC + 1][2]);
            #pragma unroll
            for (int jn = 0; jn < 8; jn++) {
                uint32_t vb[2];
                ldsm_x2t(vb, vB + (uint32_t)((mC * 16 + (lane & 15)) * 144 + jn * 16));
                mma_bf16(oa[jn], pa, vb);
            }
        }

        cp_wait0();
        __syncthreads();
    }

    float inv0 = 1.0f / l0, inv1 = 1.0f / l1;
    int grow0 = q0 + wm0 + g;
    bf16* cbase = g_ctxb + (size_t)n * SEQ * DM + h * HDIM;
    #pragma unroll
    for (int jn = 0; jn < 8; jn++) {
        int col = jn * 8 + 2 * t;
        *(uint32_t*)(cbase + (size_t)grow0 * DM + col) =
            packbf(oa[jn][1] * inv0, oa[jn][0] * inv0);
        *(uint32_t*)(cbase + (size_t)(grow0 + 8) * DM + col) =
            packbf(oa[jn][3] * inv1, oa[jn][2] * inv1);
    }
}

// ---------------- residual + rmsnorm (fp32 + bf16 outputs) ---------------------
__global__ void resid_rms_kernel(const float* __restrict__ hidden) {
    __shared__ float sh[32];
    int ns = blockIdx.x;
    int n = ns >> 10, s = ns & 1023;
    int tid = threadIdx.x;           // 256
    int d0 = tid * 4;
    size_t base = ((size_t)n * SEQ + s) * DM;
    float4 x4 = *(const float4*)(hidden + ((size_t)(n >> 1) * SEQ + s) * DM + d0);
    float4 a4 = *(const float4*)(g_ao + base + d0);
    float4 y = make_float4(x4.x + a4.x, x4.y + a4.y, x4.z + a4.z, x4.w + a4.w);
    float ss = y.x * y.x + y.y * y.y + y.z * y.z + y.w * y.w;
    ss = block_reduce_sum(ss, sh);
    float scale = rsqrtf(ss * (1.0f / (float)DM) + EPS);
    y.x *= scale; y.y *= scale; y.z *= scale; y.w *= scale;
    *(float4*)(g_x1 + base + d0) = y;
    uint2 o;
    o.x = packbf(y.y, y.x);
    o.y = packbf(y.w, y.z);
    *(uint2*)(g_x1b + base + d0) = o;
}

// ---------------- silu(gate) * up (bf16 in/out) ---------------------------------
__global__ void act_kernel() {
    int idx = blockIdx.x * blockDim.x + threadIdx.x;
    size_t r = (size_t)idx / 384;
    int i2 = (idx % 384) * 2;
    __nv_bfloat162 gv = *(const __nv_bfloat162*)(g_gub + r * (2 * INTER) + i2);
    __nv_bfloat162 uv = *(const __nv_bfloat162*)(g_gub + r * (2 * INTER) + INTER + i2);
    float g0 = __bfloat162float(gv.x), g1 = __bfloat162float(gv.y);
    float u0 = __bfloat162float(uv.x), u1 = __bfloat162float(uv.y);
    float s0 = g0 / (1.0f + __expf(-g0)) * u0;
    float s1 = g1 / (1.0f + __expf(-g1)) * u1;
    *(uint32_t*)(g_actb + r * INTER + i2) = packbf(s1, s0);
}

// ---------------- final: rmsnorm(x1 + mlp), weighted top-2 combine -------------
__global__ void final_kernel(float* __restrict__ out) {
    __shared__ float sh[32];
    int bs = blockIdx.x;
    int b = bs >> 10, s = bs & 1023;
    int tid = threadIdx.x;
    int n0 = 2 * b, n1 = 2 * b + 1;
    size_t base0 = ((size_t)n0 * SEQ + s) * DM;
    size_t base1 = ((size_t)n1 * SEQ + s) * DM;
    float y0[4], y1[4];
    float ss0 = 0.f, ss1 = 0.f;
    #pragma unroll
    for (int i = 0; i < 4; i++) {
        int d = tid + i * 256;
        y0[i] = g_x1[base0 + d] + g_mlp[base0 + d];
        y1[i] = g_x1[base1 + d] + g_mlp[base1 + d];
        ss0 = fmaf(y0[i], y0[i], ss0);
        ss1 = fmaf(y1[i], y1[i], ss1);
    }
    ss0 = block_reduce_sum(ss0, sh);
    ss1 = block_reduce_sum(ss1, sh);
    float r0 = rsqrtf(ss0 * (1.0f / (float)DM) + EPS) * g_w[n0];
    float r1 = rsqrtf(ss1 * (1.0f / (float)DM) + EPS) * g_w[n1];
    float* orow = out + ((size_t)b * SEQ + s) * DM;
    #pragma unroll
    for (int i = 0; i < 4; i++) {
        int d = tid + i * 256;
        orow[d] = y0[i] * r0 + y1[i] * r1;
    }
}

// ---------------- host launcher --------------------------------------------------
extern "C" void kernel_launch(void* const* d_in, const int* in_sizes, int n_in,
                              void* d_out, int out_size) {
    const float* hidden = (const float*)d_in[0];
    const float* cosb   = (const float*)d_in[1];
    const float* sinb   = (const float*)d_in[2];
    const float* Wr     = (const float*)d_in[3];
    const float* temp   = (const float*)d_in[4];
    const float* Wqkv   = (const float*)d_in[5];
    const float* Wo     = (const float*)d_in[6];
    const float* Wgu    = (const float*)d_in[7];
    const float* Wd     = (const float*)d_in[8];
    float* out = (float*)d_out;

    bf16 *p_hb, *p_qkvb, *p_ctxb, *p_x1b, *p_gub, *p_actb, *p_wb;
    float *p_ao, *p_x1, *p_mlp;
    cudaGetSymbolAddress((void**)&p_hb,   g_hb);
    cudaGetSymbolAddress((void**)&p_qkvb, g_qkvb);
    cudaGetSymbolAddress((void**)&p_ctxb, g_ctxb);
    cudaGetSymbolAddress((void**)&p_x1b,  g_x1b);
    cudaGetSymbolAddress((void**)&p_gub,  g_gub);
    cudaGetSymbolAddress((void**)&p_actb, g_actb);
    cudaGetSymbolAddress((void**)&p_wb,   g_wb);
    cudaGetSymbolAddress((void**)&p_ao,   g_ao);
    cudaGetSymbolAddress((void**)&p_x1,   g_x1);
    cudaGetSymbolAddress((void**)&p_mlp,  g_mlp);

    cudaFuncSetAttribute(flash_kernel,
                         cudaFuncAttributeMaxDynamicSharedMemorySize, FLASH_SMEM);
    cudaFuncSetAttribute((const void*)gemm_bf<0>,
                         cudaFuncAttributeMaxDynamicSharedMemorySize, GEMM_SMEM);
    cudaFuncSetAttribute((const void*)gemm_bf<1>,
                         cudaFuncAttributeMaxDynamicSharedMemorySize, GEMM_SMEM);

    // routing first (sets g_need for routed-only weight conversion)
    mean1_kernel<<<dim3(BATCH, 16), 256>>>(hidden);
    mean2_kernel<<<BATCH, 256>>>();
    routing_kernel<<<1, 1024>>>(Wr, temp, out + (size_t)BATCH * SEQ * DM);

    // bf16 conversions
    {
        int n4 = BATCH * SEQ * DM / 4;
        cvt_bf16<<<(n4 + 255) / 256, 256>>>((const float4*)hidden, (uint2*)p_hb, n4);
        n4 = 8 * DM * 3 * DM / 4;
        cvt_w<<<(n4 + 255) / 256, 256>>>((const float4*)Wqkv, (uint2*)(p_wb + WB_QKV),
                                         n4, DM * 3 * DM / 4);
        n4 = 8 * DM * DM / 4;
        cvt_w<<<(n4 + 255) / 256, 256>>>((const float4*)Wo, (uint2*)(p_wb + WB_WO),
                                         n4, DM * DM / 4);
        n4 = 8 * DM * 2 * INTER / 4;
        cvt_w<<<(n4 + 255) / 256, 256>>>((const float4*)Wgu, (uint2*)(p_wb + WB_GU),
                                         n4, DM * 2 * INTER / 4);
        n4 = 8 * INTER * DM / 4;
        cvt_w<<<(n4 + 255) / 256, 256>>>((const float4*)Wd, (uint2*)(p_wb + WB_WD),
                                         n4, INTER * DM / 4);
    }

    // qkv = x @ Wqkv[e]   (bf16 out)
    gemm_bf<1><<<dim3(3072 / 128, SEQ / 256, NSAMP), 256, GEMM_SMEM>>>(
        p_hb, p_wb + WB_QKV, p_qkvb, 3 * DM, DM, DM,
        (long long)SEQ * DM, 1, (long long)SEQ * 3 * DM);

    // rope in-place (bf16)
    rope_kernel<<<dim3(SEQ, NSAMP), 512>>>(cosb, sinb);

    // fused attention -> g_ctxb (bf16)
    flash_kernel<<<dim3(SEQ / 64, NSAMP * HN), 128, FLASH_SMEM>>>();

    // attn_out = ctx @ Wo[e]  (fp32 out)
    gemm_bf<0><<<dim3(DM / 128, SEQ / 256, NSAMP), 256, GEMM_SMEM>>>(
        p_ctxb, p_wb + WB_WO, p_ao, DM, DM, DM,
        (long long)SEQ * DM, 0, (long long)SEQ * DM);

    // x1 = rmsnorm(x + attn_out)  (fp32 + bf16 outs)
    resid_rms_kernel<<<NSAMP * SEQ, 256>>>(hidden);

    // gu = x1 @ Wgu[e]  (bf16 out)
    gemm_bf<1><<<dim3(2 * INTER / 128, SEQ / 256, NSAMP), 256, GEMM_SMEM>>>(
        p_x1b, p_wb + WB_GU, p_gub, 2 * INTER, DM, DM,
        (long long)SEQ * DM, 0, (long long)SEQ * 2 * INTER);

    // act = silu(gate) * up  (bf16 out)
    act_kernel<<<(NSAMP * SEQ * INTER / 2) / 256, 256>>>();

    // mlp = act @ Wd[e]  (fp32 out)
    gemm_bf<0><<<dim3(DM / 128, SEQ / 256, NSAMP), 256, GEMM_SMEM>>>(
        p_actb, p_wb + WB_WD, p_mlp, DM, INTER, INTER,
        (long long)SEQ * INTER, 0, (long long)SEQ * DM);

    // out = sum of weighted rmsnorm(x1 + mlp)
    final_kernel<<<BATCH * SEQ, 256>>>(out);
}

// round 9
// speedup vs baseline: 1.0639x; 1.0639x over previous
#include <cuda_runtime.h>
#include <cuda_bf16.h>
#include <math.h>
#include <stdint.h>

#define SEQ   1024
#define DM    1024
#define HN    16
#define HDIM  64
#define NSAMP 8
#define INTER 768
#define BATCH 4
#define EPS   1e-5f

typedef __nv_bfloat16 bf16;

// ---------------- scratch (device globals; no allocations allowed) ----------
__device__ float g_hsmean[BATCH * DM];
__device__ float g_partial[BATCH * 16 * DM];
__device__ int   g_expert[NSAMP];
__device__ int   g_need[8];
__device__ float g_w[NSAMP];
__device__ bf16  g_hb[(size_t)BATCH * SEQ * DM];
__device__ bf16  g_qkvb[(size_t)NSAMP * SEQ * 3 * DM];       // 48 MB
__device__ bf16  g_ctxb[(size_t)NSAMP * SEQ * DM];           // 16 MB
__device__ float g_ao[(size_t)NSAMP * SEQ * DM];             // 32 MB
__device__ float g_x1[(size_t)NSAMP * SEQ * DM];             // 32 MB
__device__ bf16  g_x1b[(size_t)NSAMP * SEQ * DM];            // 16 MB
__device__ bf16  g_gub[(size_t)NSAMP * SEQ * 2 * INTER];     // 24 MB
__device__ bf16  g_actb[(size_t)NSAMP * SEQ * INTER];        // 12 MB
__device__ float g_mlp[(size_t)NSAMP * SEQ * DM];            // 32 MB
// all-expert bf16 weights
#define WB_QKV 0LL
#define WB_WO  25165824LL
#define WB_GU  33554432LL
#define WB_WD  46137344LL
#define WB_TOTAL 52428800LL
__device__ bf16 g_wb[WB_TOTAL];                              // 105 MB

// ---------------- small helpers ----------------------------------------------
__device__ __forceinline__ float block_reduce_sum(float v, float* sh) {
    int tid = threadIdx.x;
    #pragma unroll
    for (int o = 16; o; o >>= 1) v += __shfl_down_sync(0xFFFFFFFFu, v, o);
    if ((tid & 31) == 0) sh[tid >> 5] = v;
    __syncthreads();
    float r = 0.f;
    if (tid < 32) {
        float x = (tid < (int)(blockDim.x >> 5)) ? sh[tid] : 0.f;
        #pragma unroll
        for (int o = 16; o; o >>= 1) x += __shfl_down_sync(0xFFFFFFFFu, x, o);
        if (tid == 0) sh[0] = x;
    }
    __syncthreads();
    r = sh[0];
    __syncthreads();
    return r;
}

__device__ __forceinline__ void mma_bf16(float* d, const uint32_t* a, const uint32_t* b) {
    asm volatile(
        "mma.sync.aligned.m16n8k16.row.col.f32.bf16.bf16.f32 "
        "{%0,%1,%2,%3},{%4,%5,%6,%7},{%8,%9},{%0,%1,%2,%3};"
        : "+f"(d[0]), "+f"(d[1]), "+f"(d[2]), "+f"(d[3])
        : "r"(a[0]), "r"(a[1]), "r"(a[2]), "r"(a[3]), "r"(b[0]), "r"(b[1]));
}

__device__ __forceinline__ void ldsm_x4(uint32_t* r, uint32_t addr) {
    asm volatile(
        "ldmatrix.sync.aligned.m8n8.x4.shared.b16 {%0,%1,%2,%3}, [%4];"
        : "=r"(r[0]), "=r"(r[1]), "=r"(r[2]), "=r"(r[3]) : "r"(addr));
}
__device__ __forceinline__ void ldsm_x2t(uint32_t* r, uint32_t addr) {
    asm volatile(
        "ldmatrix.sync.aligned.m8n8.x2.trans.shared.b16 {%0,%1}, [%2];"
        : "=r"(r[0]), "=r"(r[1]) : "r"(addr));
}
__device__ __forceinline__ uint32_t lds32(uint32_t a) {
    uint32_t v;
    asm volatile("ld.shared.b32 %0, [%1];" : "=r"(v) : "r"(a));
    return v;
}
__device__ __forceinline__ uint32_t packbf(float hi, float lo) {
    uint32_t r;
    asm("cvt.rn.bf16x2.f32 %0, %1, %2;" : "=r"(r) : "f"(hi), "f"(lo));
    return r;
}

__device__ __forceinline__ void cp16(uint32_t s, const void* g) {
    asm volatile("cp.async.cg.shared.global [%0], [%1], 16;" :: "r"(s), "l"(g));
}
__device__ __forceinline__ void cp_commit() {
    asm volatile("cp.async.commit_group;" ::: "memory");
}
__device__ __forceinline__ void cp_wait0() {
    asm volatile("cp.async.wait_group 0;" ::: "memory");
}
__device__ __forceinline__ void cp_wait1() {
    asm volatile("cp.async.wait_group 1;" ::: "memory");
}

// ---------------- fp32 -> bf16 conversion ------------------------------------
__global__ void cvt_bf16(const float4* __restrict__ s, uint2* __restrict__ d, int n4) {
    int i = blockIdx.x * blockDim.x + threadIdx.x;
    if (i < n4) {
        float4 v = s[i];
        uint2 o;
        o.x = packbf(v.y, v.x);
        o.y = packbf(v.w, v.z);
        d[i] = o;
    }
}

// convert expert weights only if routed (g_need flag)
__global__ void cvt_w(const float4* __restrict__ s, uint2* __restrict__ d,
                      int n4, int perExp4) {
    int i = blockIdx.x * blockDim.x + threadIdx.x;
    if (i >= n4) return;
    if (!g_need[i / perExp4]) return;
    float4 v = s[i];
    uint2 o;
    o.x = packbf(v.y, v.x);
    o.y = packbf(v.w, v.z);
    d[i] = o;
}

// ---------------- routing ----------------------------------------------------
__global__ void mean1_kernel(const float* __restrict__ hidden) {
    int b = blockIdx.x, c = blockIdx.y;
    int tid = threadIdx.x;
    float acc[4] = {0.f, 0.f, 0.f, 0.f};
    for (int s = c * 64; s < c * 64 + 64; s++) {
        const float* row = hidden + ((size_t)b * SEQ + s) * DM;
        #pragma unroll
        for (int i = 0; i < 4; i++) acc[i] += row[tid + i * 256];
    }
    #pragma unroll
    for (int i = 0; i < 4; i++)
        g_partial[((size_t)b * 16 + c) * DM + tid + i * 256] = acc[i];
}

__global__ void mean2_kernel() {
    int b = blockIdx.x;
    int tid = threadIdx.x;
    #pragma unroll
    for (int i = 0; i < 4; i++) {
        int d = tid + i * 256;
        float s = 0.f;
        for (int c = 0; c < 16; c++) s += g_partial[((size_t)b * 16 + c) * DM + d];
        g_hsmean[b * DM + d] = s * (1.0f / (float)SEQ);
    }
}

__global__ void routing_kernel(const float* __restrict__ Wr,
                               const float* __restrict__ temperature,
                               float* __restrict__ out_logits) {
    int tid = threadIdx.x;          // 1024
    int w = tid >> 5, lane = tid & 31;
    int b = w >> 3, c = w & 7;
    float s = 0.f;
    for (int d = lane; d < DM; d += 32)
        s += g_hsmean[b * DM + d] * Wr[c * DM + d];
    #pragma unroll
    for (int o = 16; o; o >>= 1) s += __shfl_down_sync(0xFFFFFFFFu, s, o);
    __shared__ float logits[32];
    if (lane == 0) logits[w] = s;
    if (tid < 8) g_need[tid] = 0;
    __syncthreads();
    if (tid < BATCH) {
        float t = fminf(fmaxf(temperature[0], 0.1f), 10.0f);
        float lv[8];
        #pragma unroll
        for (int cc = 0; cc < 8; cc++) {
            lv[cc] = logits[tid * 8 + cc] / t;
            out_logits[tid * 8 + cc] = lv[cc];
        }
        int i0 = 0;
        #pragma unroll
        for (int cc = 1; cc < 8; cc++) if (lv[cc] > lv[i0]) i0 = cc;
        int i1 = -1;
        #pragma unroll
        for (int cc = 0; cc < 8; cc++) {
            if (cc == i0) continue;
            if (i1 < 0 || lv[cc] > lv[i1]) i1 = cc;
        }
        float e = expf(lv[i1] - lv[i0]);
        g_expert[2 * tid]     = i0;
        g_expert[2 * tid + 1] = i1;
        g_w[2 * tid]     = 1.0f / (1.0f + e);
        g_w[2 * tid + 1] = e / (1.0f + e);
        g_need[i0] = 1;
        g_need[i1] = 1;
    }
}

// ---------------- bf16 tensor-core GEMM (round-7 config) -----------------------
// BM=BN=128, BK=64, 3-stage cp.async, ldsm A (x4) + ldsm.trans B (x2), 2 CTA/SM.
#define ASTG 144                    // A row stride bytes (64 bf16 + 8 pad)
#define BSTG 272                    // B row stride bytes (128 bf16 + 8 pad)
#define ABYTES (128 * ASTG)         // 18432
#define BBYTES (64 * BSTG)          // 17408
#define STGB (ABYTES + BBYTES)      // 35840
#define GEMM_SMEM (3 * STGB)        // 107520

template<int OBF>
__global__ __launch_bounds__(256, 2) void gemm_bf(
    const bf16* __restrict__ Ab, const bf16* __restrict__ Bb, void* __restrict__ Cb,
    int N, int K, int lda, long long strideA, int a_div2, long long strideC)
{
    extern __shared__ char smraw[];
    uint32_t sb = (uint32_t)__cvta_generic_to_shared(smraw);
    int z = blockIdx.z;
    const bf16* A = Ab + (size_t)(a_div2 ? (z >> 1) : z) * strideA;
    const bf16* B = Bb + (long long)g_expert[z] * ((long long)K * N);
    int m0 = blockIdx.y * 128;
    int n0 = blockIdx.x * 128;
    int tid = threadIdx.x, lane = tid & 31, wid = tid >> 5;
    int wm0 = (wid & 1) * 64;       // warp tile 64x32
    int wn0 = (wid >> 1) * 32;
    int g = lane >> 2, t = lane & 3;

    auto load_tile = [&](int k0, int buf) {
        uint32_t base = sb + (uint32_t)(buf * STGB);
        #pragma unroll
        for (int p = 0; p < 4; p++) {
            int i = tid + p * 256;
            int row = i >> 3, ch = i & 7;
            cp16(base + (uint32_t)(row * ASTG + ch * 16),
                 A + (size_t)(m0 + row) * lda + k0 + ch * 8);
        }
        #pragma unroll
        for (int p = 0; p < 4; p++) {
            int i = tid + p * 256;
            int row = i >> 4, ch = i & 15;
            cp16(base + (uint32_t)(ABYTES + row * BSTG + ch * 16),
                 B + (size_t)(k0 + row) * N + n0 + ch * 8);
        }
    };

    int NT = K / 64;
    load_tile(0, 0);
    cp_commit();
    load_tile(64, 1);
    cp_commit();

    float acc[4][4][4];
    #pragma unroll
    for (int i = 0; i < 4; i++)
        #pragma unroll
        for (int j = 0; j < 4; j++)
            #pragma unroll
            for (int q = 0; q < 4; q++) acc[i][j][q] = 0.f;

    uint32_t af[2][4][4];
    uint32_t bfr[2][4][2];

    int buf = 0;
    for (int tI = 0; tI < NT; ++tI) {
        if (tI + 1 < NT) cp_wait1(); else cp_wait0();
        __syncthreads();
        if (tI + 2 < NT) {
            int nb = buf + 2; if (nb >= 3) nb -= 3;
            load_tile((tI + 2) * 64, nb);
            cp_commit();
        }
        uint32_t stage = sb + (uint32_t)(buf * STGB);
        uint32_t aB = stage + (uint32_t)((wm0 + (lane & 15)) * ASTG + (lane >> 4) * 16);
        uint32_t bB = stage + (uint32_t)(ABYTES + (lane & 15) * BSTG + wn0 * 2);

        #pragma unroll
        for (int i = 0; i < 4; i++) ldsm_x4(af[0][i], aB + (uint32_t)(i * 16 * ASTG));
        #pragma unroll
        for (int j = 0; j < 4; j++) ldsm_x2t(bfr[0][j], bB + (uint32_t)(j * 16));

        #pragma unroll
        for (int ks = 0; ks < 4; ks++) {
            int cb = ks & 1, nb2 = cb ^ 1;
            if (ks < 3) {
                #pragma unroll
                for (int i = 0; i < 4; i++)
                    ldsm_x4(af[nb2][i], aB + (uint32_t)(i * 16 * ASTG + (ks + 1) * 32));
                #pragma unroll
                for (int j = 0; j < 4; j++)
                    ldsm_x2t(bfr[nb2][j], bB + (uint32_t)((ks + 1) * 16 * BSTG + j * 16));
            }
            #pragma unroll
            for (int i = 0; i < 4; i++)
                #pragma unroll
                for (int j = 0; j < 4; j++)
                    mma_bf16(acc[i][j], af[cb][i], bfr[cb][j]);
        }
        buf++; if (buf == 3) buf = 0;
    }

    #pragma unroll
    for (int i = 0; i < 4; i++) {
        #pragma unroll
        for (int j = 0; j < 4; j++) {
            int r = m0 + wm0 + i * 16 + g;
            int c = n0 + wn0 + j * 8 + 2 * t;
            if (OBF) {
                bf16* C = (bf16*)Cb + (size_t)z * strideC;
                *(uint32_t*)(C + (size_t)r * N + c) = packbf(acc[i][j][1], acc[i][j][0]);
                *(uint32_t*)(C + (size_t)(r + 8) * N + c) = packbf(acc[i][j][3], acc[i][j][2]);
            } else {
                float* C = (float*)Cb + (size_t)z * strideC;
                *(float2*)(C + (size_t)r * N + c) = make_float2(acc[i][j][0], acc[i][j][1]);
                *(float2*)(C + (size_t)(r + 8) * N + c) = make_float2(acc[i][j][2], acc[i][j][3]);
            }
        }
    }
}

// ---------------- RoPE (in-place on bf16 q,k) ---------------------------------
__global__ void rope_kernel(const float* __restrict__ cosb, const float* __restrict__ sinb) {
    int s = blockIdx.x, n = blockIdx.y;
    int tid = threadIdx.x;            // 512
    int h = tid >> 5, j = tid & 31;
    float c0 = cosb[s * HDIM + j],      s0 = sinb[s * HDIM + j];
    float c1 = cosb[s * HDIM + j + 32], s1 = sinb[s * HDIM + j + 32];
    bf16* row = g_qkvb + ((size_t)n * SEQ + s) * (3 * DM);
    bf16* q = row + h * HDIM;
    float qa = __bfloat162float(q[j]), qb = __bfloat162float(q[j + 32]);
    q[j]      = __float2bfloat16(qa * c0 - qb * s0);
    q[j + 32] = __float2bfloat16(qb * c1 + qa * s1);
    bf16* k = row + DM + h * HDIM;
    float ka = __bfloat162float(k[j]), kb = __bfloat162float(k[j + 32]);
    k[j]      = __float2bfloat16(ka * c0 - kb * s0);
    k[j + 32] = __float2bfloat16(kb * c1 + ka * s1);
}

// ---------------- flash attention (bf16 mma) -----------------------------------
#define FQ 0
#define FK 9216
#define FV (9216 * 3)
#define FLASH_SMEM (9216 * 5)

__global__ __launch_bounds__(128) void flash_kernel() {
    extern __shared__ char smraw[];
    uint32_t sb = (uint32_t)__cvta_generic_to_shared(smraw);

    int nh = blockIdx.y;
    int n = nh >> 4, h = nh & 15;
    int q0 = blockIdx.x * 64;
    const bf16* qbase = g_qkvb + (size_t)n * SEQ * (3 * DM) + h * HDIM;
    const bf16* kbase = qbase + DM;
    const bf16* vbase = qbase + 2 * DM;

    int tid = threadIdx.x, lane = tid & 31, wid = tid >> 5;
    int g = lane >> 2, t = lane & 3;
    int wm0 = wid * 16;

    #pragma unroll
    for (int p = 0; p < 4; p++) {
        int i = tid + p * 128;
        int row = i >> 3, ch = i & 7;
        cp16(sb + (uint32_t)(FQ + row * 144 + ch * 16),
             qbase + (size_t)(q0 + row) * (3 * DM) + ch * 8);
        cp16(sb + (uint32_t)(FK + row * 144 + ch * 16),
             kbase + (size_t)row * (3 * DM) + ch * 8);
        cp16(sb + (uint32_t)(FV + row * 144 + ch * 16),
             vbase + (size_t)row * (3 * DM) + ch * 8);
    }
    cp_commit();
    cp_wait0();
    __syncthreads();

    uint32_t qf[4][4];
    uint32_t qA = sb + (uint32_t)(FQ + (wm0 + (lane & 15)) * 144 + (lane >> 4) * 16);
    #pragma unroll
    for (int kc = 0; kc < 4; kc++) ldsm_x4(qf[kc], qA + (uint32_t)(kc * 32));

    float m0 = -INFINITY, m1 = -INFINITY, l0 = 0.f, l1 = 0.f;
    float oa[8][4];
    #pragma unroll
    for (int j = 0; j < 8; j++)
        #pragma unroll
        for (int q = 0; q < 4; q++) oa[j][q] = 0.f;

    const int NT = SEQ / 64;
    for (int it = 0; it < NT; it++) {
        int buf = it & 1;
        if (it + 1 < NT) {
            int kv = (it + 1) * 64;
            int ob = buf ^ 1;
            #pragma unroll
            for (int p = 0; p < 4; p++) {
                int i = tid + p * 128;
                int row = i >> 3, ch = i & 7;
                cp16(sb + (uint32_t)(FK + ob * 9216 + row * 144 + ch * 16),
                     kbase + (size_t)(kv + row) * (3 * DM) + ch * 8);
                cp16(sb + (uint32_t)(FV + ob * 9216 + row * 144 + ch * 16),
                     vbase + (size_t)(kv + row) * (3 * DM) + ch * 8);
            }
            cp_commit();
        }
        uint32_t kB = sb + (uint32_t)(FK + buf * 9216);
        uint32_t vB = sb + (uint32_t)(FV + buf * 9216);

        float sacc[8][4];
        #pragma unroll
        for (int j = 0; j < 8; j++)
            #pragma unroll
            for (int q = 0; q < 4; q++) sacc[j][q] = 0.f;

        #pragma unroll
        for (int kc = 0; kc < 4; kc++) {
            #pragma unroll
            for (int nt = 0; nt < 8; nt++) {
                uint32_t ba = kB + (uint32_t)((nt * 8 + g) * 144 + kc * 32 + t * 4);
                uint32_t bb[2];
                bb[0] = lds32(ba);
                bb[1] = lds32(ba + 16);
                mma_bf16(sacc[nt], qf[kc], bb);
            }
        }

        float rm0 = -INFINITY, rm1 = -INFINITY;
        #pragma unroll
        for (int nt = 0; nt < 8; nt++) {
            #pragma unroll
            for (int q = 0; q < 4; q++) sacc[nt][q] *= 0.125f;
            rm0 = fmaxf(rm0, fmaxf(sacc[nt][0], sacc[nt][1]));
            rm1 = fmaxf(rm1, fmaxf(sacc[nt][2], sacc[nt][3]));
        }
        rm0 = fmaxf(rm0, __shfl_xor_sync(0xFFFFFFFFu, rm0, 1));
        rm0 = fmaxf(rm0, __shfl_xor_sync(0xFFFFFFFFu, rm0, 2));
        rm1 = fmaxf(rm1, __shfl_xor_sync(0xFFFFFFFFu, rm1, 1));
        rm1 = fmaxf(rm1, __shfl_xor_sync(0xFFFFFFFFu, rm1, 2));
        float mn0 = fmaxf(m0, rm0), mn1 = fmaxf(m1, rm1);
        float c0 = __expf(m0 - mn0), c1 = __expf(m1 - mn1);
        float ls0 = 0.f, ls1 = 0.f;
        #pragma unroll
        for (int nt = 0; nt < 8; nt++) {
            sacc[nt][0] = __expf(sacc[nt][0] - mn0);
            sacc[nt][1] = __expf(sacc[nt][1] - mn0);
            sacc[nt][2] = __expf(sacc[nt][2] - mn1);
            sacc[nt][3] = __expf(sacc[nt][3] - mn1);
            ls0 += sacc[nt][0] + sacc[nt][1];
            ls1 += sacc[nt][2] + sacc[nt][3];
        }
        ls0 += __shfl_xor_sync(0xFFFFFFFFu, ls0, 1);
        ls0 += __shfl_xor_sync(0xFFFFFFFFu, ls0, 2);
        ls1 += __shfl_xor_sync(0xFFFFFFFFu, ls1, 1);
        ls1 += __shfl_xor_sync(0xFFFFFFFFu, ls1, 2);
        l0 = l0 * c0 + ls0;
        l1 = l1 * c1 + ls1;
        m0 = mn0; m1 = mn1;
        #pragma unroll
        for (int j = 0; j < 8; j++) {
            oa[j][0] *= c0; oa[j][1] *= c0;
            oa[j][2] *= c1; oa[j][3] *= c1;
        }

        #pragma unroll
        for (int mC = 0; mC < 4; mC++) {
            uint32_t pa[4];
            pa[0] = packbf(sacc[2 * mC][1],     sacc[2 * mC][0]);
            pa[1] = packbf(sacc[2 * mC][3],     sacc[2 * mC][2]);
            pa[2] = packbf(sacc[2 * mC + 1][1], sacc[2 * mC + 1][0]);
            pa[3] = packbf(sacc[2 * mC + 1][3], sacc[2 * mC + 1][2]);
            #pragma unroll
            for (int jn = 0; jn < 8; jn++) {
                uint32_t vb[2];
                ldsm_x2t(vb, vB + (uint32_t)((mC * 16 + (lane & 15)) * 144 + jn * 16));
                mma_bf16(oa[jn], pa, vb);
            }
        }

        cp_wait0();
        __syncthreads();
    }

    float inv0 = 1.0f / l0, inv1 = 1.0f / l1;
    int grow0 = q0 + wm0 + g;
    bf16* cbase = g_ctxb + (size_t)n * SEQ * DM + h * HDIM;
    #pragma unroll
    for (int jn = 0; jn < 8; jn++) {
        int col = jn * 8 + 2 * t;
        *(uint32_t*)(cbase + (size_t)grow0 * DM + col) =
            packbf(oa[jn][1] * inv0, oa[jn][0] * inv0);
        *(uint32_t*)(cbase + (size_t)(grow0 + 8) * DM + col) =
            packbf(oa[jn][3] * inv1, oa[jn][2] * inv1);
    }
}

// ---------------- residual + rmsnorm (fp32 + bf16 outputs) ---------------------
__global__ void resid_rms_kernel(const float* __restrict__ hidden) {
    __shared__ float sh[32];
    int ns = blockIdx.x;
    int n = ns >> 10, s = ns & 1023;
    int tid = threadIdx.x;           // 256
    int d0 = tid * 4;
    size_t base = ((size_t)n * SEQ + s) * DM;
    float4 x4 = *(const float4*)(hidden + ((size_t)(n >> 1) * SEQ + s) * DM + d0);
    float4 a4 = *(const float4*)(g_ao + base + d0);
    float4 y = make_float4(x4.x + a4.x, x4.y + a4.y, x4.z + a4.z, x4.w + a4.w);
    float ss = y.x * y.x + y.y * y.y + y.z * y.z + y.w * y.w;
    ss = block_reduce_sum(ss, sh);
    float scale = rsqrtf(ss * (1.0f / (float)DM) + EPS);
    y.x *= scale; y.y *= scale; y.z *= scale; y.w *= scale;
    *(float4*)(g_x1 + base + d0) = y;
    uint2 o;
    o.x = packbf(y.y, y.x);
    o.y = packbf(y.w, y.z);
    *(uint2*)(g_x1b + base + d0) = o;
}

// ---------------- silu(gate) * up (bf16 in/out) ---------------------------------
__global__ void act_kernel() {
    int idx = blockIdx.x * blockDim.x + threadIdx.x;
    size_t r = (size_t)idx / 384;
    int i2 = (idx % 384) * 2;
    __nv_bfloat162 gv = *(const __nv_bfloat162*)(g_gub + r * (2 * INTER) + i2);
    __nv_bfloat162 uv = *(const __nv_bfloat162*)(g_gub + r * (2 * INTER) + INTER + i2);
    float g0 = __bfloat162float(gv.x), g1 = __bfloat162float(gv.y);
    float u0 = __bfloat162float(uv.x), u1 = __bfloat162float(uv.y);
    float s0 = g0 / (1.0f + __expf(-g0)) * u0;
    float s1 = g1 / (1.0f + __expf(-g1)) * u1;
    *(uint32_t*)(g_actb + r * INTER + i2) = packbf(s1, s0);
}

// ---------------- final: rmsnorm(x1 + mlp), weighted top-2 combine -------------
__global__ void final_kernel(float* __restrict__ out) {
    __shared__ float sh[32];
    int bs = blockIdx.x;
    int b = bs >> 10, s = bs & 1023;
    int tid = threadIdx.x;
    int n0 = 2 * b, n1 = 2 * b + 1;
    size_t base0 = ((size_t)n0 * SEQ + s) * DM;
    size_t base1 = ((size_t)n1 * SEQ + s) * DM;
    float y0[4], y1[4];
    float ss0 = 0.f, ss1 = 0.f;
    #pragma unroll
    for (int i = 0; i < 4; i++) {
        int d = tid + i * 256;
        y0[i] = g_x1[base0 + d] + g_mlp[base0 + d];
        y1[i] = g_x1[base1 + d] + g_mlp[base1 + d];
        ss0 = fmaf(y0[i], y0[i], ss0);
        ss1 = fmaf(y1[i], y1[i], ss1);
    }
    ss0 = block_reduce_sum(ss0, sh);
    ss1 = block_reduce_sum(ss1, sh);
    float r0 = rsqrtf(ss0 * (1.0f / (float)DM) + EPS) * g_w[n0];
    float r1 = rsqrtf(ss1 * (1.0f / (float)DM) + EPS) * g_w[n1];
    float* orow = out + ((size_t)b * SEQ + s) * DM;
    #pragma unroll
    for (int i = 0; i < 4; i++) {
        int d = tid + i * 256;
        orow[d] = y0[i] * r0 + y1[i] * r1;
    }
}

// ---------------- host launcher --------------------------------------------------
extern "C" void kernel_launch(void* const* d_in, const int* in_sizes, int n_in,
                              void* d_out, int out_size) {
    const float* hidden = (const float*)d_in[0];
    const float* cosb   = (const float*)d_in[1];
    const float* sinb   = (const float*)d_in[2];
    const float* Wr     = (const float*)d_in[3];
    const float* temp   = (const float*)d_in[4];
    const float* Wqkv   = (const float*)d_in[5];
    const float* Wo     = (const float*)d_in[6];
    const float* Wgu    = (const float*)d_in[7];
    const float* Wd     = (const float*)d_in[8];
    float* out = (float*)d_out;

    bf16 *p_hb, *p_qkvb, *p_ctxb, *p_x1b, *p_gub, *p_actb, *p_wb;
    float *p_ao, *p_x1, *p_mlp;
    cudaGetSymbolAddress((void**)&p_hb,   g_hb);
    cudaGetSymbolAddress((void**)&p_qkvb, g_qkvb);
    cudaGetSymbolAddress((void**)&p_ctxb, g_ctxb);
    cudaGetSymbolAddress((void**)&p_x1b,  g_x1b);
    cudaGetSymbolAddress((void**)&p_gub,  g_gub);
    cudaGetSymbolAddress((void**)&p_actb, g_actb);
    cudaGetSymbolAddress((void**)&p_wb,   g_wb);
    cudaGetSymbolAddress((void**)&p_ao,   g_ao);
    cudaGetSymbolAddress((void**)&p_x1,   g_x1);
    cudaGetSymbolAddress((void**)&p_mlp,  g_mlp);

    cudaFuncSetAttribute(flash_kernel,
                         cudaFuncAttributeMaxDynamicSharedMemorySize, FLASH_SMEM);
    cudaFuncSetAttribute((const void*)gemm_bf<0>,
                         cudaFuncAttributeMaxDynamicSharedMemorySize, GEMM_SMEM);
    cudaFuncSetAttribute((const void*)gemm_bf<1>,
                         cudaFuncAttributeMaxDynamicSharedMemorySize, GEMM_SMEM);

    // routing first (sets g_need for routed-only weight conversion)
    mean1_kernel<<<dim3(BATCH, 16), 256>>>(hidden);
    mean2_kernel<<<BATCH, 256>>>();
    routing_kernel<<<1, 1024>>>(Wr, temp, out + (size_t)BATCH * SEQ * DM);

    // bf16 conversions
    {
        int n4 = BATCH * SEQ * DM / 4;
        cvt_bf16<<<(n4 + 255) / 256, 256>>>((const float4*)hidden, (uint2*)p_hb, n4);
        n4 = 8 * DM * 3 * DM / 4;
        cvt_w<<<(n4 + 255) / 256, 256>>>((const float4*)Wqkv, (uint2*)(p_wb + WB_QKV),
                                         n4, DM * 3 * DM / 4);
        n4 = 8 * DM * DM / 4;
        cvt_w<<<(n4 + 255) / 256, 256>>>((const float4*)Wo, (uint2*)(p_wb + WB_WO),
                                         n4, DM * DM / 4);
        n4 = 8 * DM * 2 * INTER / 4;
        cvt_w<<<(n4 + 255) / 256, 256>>>((const float4*)Wgu, (uint2*)(p_wb + WB_GU),
                                         n4, DM * 2 * INTER / 4);
        n4 = 8 * INTER * DM / 4;
        cvt_w<<<(n4 + 255) / 256, 256>>>((const float4*)Wd, (uint2*)(p_wb + WB_WD),
                                         n4, INTER * DM / 4);
    }

    // qkv = x @ Wqkv[e]   (bf16 out)
    gemm_bf<1><<<dim3(3072 / 128, SEQ / 128, NSAMP), 256, GEMM_SMEM>>>(
        p_hb, p_wb + WB_QKV, p_qkvb, 3 * DM, DM, DM,
        (long long)SEQ * DM, 1, (long long)SEQ * 3 * DM);

    // rope in-place (bf16)
    rope_kernel<<<dim3(SEQ, NSAMP), 512>>>(cosb, sinb);

    // fused attention -> g_ctxb (bf16)
    flash_kernel<<<dim3(SEQ / 64, NSAMP * HN), 128, FLASH_SMEM>>>();

    // attn_out = ctx @ Wo[e]  (fp32 out)
    gemm_bf<0><<<dim3(DM / 128, SEQ / 128, NSAMP), 256, GEMM_SMEM>>>(
        p_ctxb, p_wb + WB_WO, p_ao, DM, DM, DM,
        (long long)SEQ * DM, 0, (long long)SEQ * DM);

    // x1 = rmsnorm(x + attn_out)  (fp32 + bf16 outs)
    resid_rms_kernel<<<NSAMP * SEQ, 256>>>(hidden);

    // gu = x1 @ Wgu[e]  (bf16 out)
    gemm_bf<1><<<dim3(2 * INTER / 128, SEQ / 128, NSAMP), 256, GEMM_SMEM>>>(
        p_x1b, p_wb + WB_GU, p_gub, 2 * INTER, DM, DM,
        (long long)SEQ * DM, 0, (long long)SEQ * 2 * INTER);

    // act = silu(gate) * up  (bf16 out)
    act_kernel<<<(NSAMP * SEQ * INTER / 2) / 256, 256>>>();

    // mlp = act @ Wd[e]  (fp32 out)
    gemm_bf<0><<<dim3(DM / 128, SEQ / 128, NSAMP), 256, GEMM_SMEM>>>(
        p_actb, p_wb + WB_WD, p_mlp, DM, INTER, INTER,
        (long long)SEQ * INTER, 0, (long long)SEQ * DM);

    // out = sum of weighted rmsnorm(x1 + mlp)
    final_kernel<<<BATCH * SEQ, 256>>>(out);
}